// round 6
// baseline (speedup 1.0000x reference)
#include <cuda_runtime.h>

#define NGRID   41088
#define PMAX    404
#define MDIM    192
#define KR      192
#define BCN     1024
#define TWO_PI_F 6.28318530717958647692f

typedef unsigned long long u64;
typedef unsigned int u32;

// Stage-A output: (re,im) pairs, layout [m][k][bc]
__device__ u64 g_ri[(size_t)MDIM * KR * BCN];
// Stage-B staging: (re,im) pairs, layout [m][l][bc]
__device__ u64 g_st[(size_t)MDIM * MDIM * BCN];

__device__ __forceinline__ u64 ffma2(u64 a, u64 b, u64 c) {
    u64 d; asm("fma.rn.f32x2 %0,%1,%2,%3;" : "=l"(d) : "l"(a), "l"(b), "l"(c)); return d;
}
__device__ __forceinline__ u64 fmul2(u64 a, u64 b) {
    u64 d; asm("mul.rn.f32x2 %0,%1,%2;" : "=l"(d) : "l"(a), "l"(b)); return d;
}
__device__ __forceinline__ u64 fadd2(u64 a, u64 b) {
    u64 d; asm("add.rn.f32x2 %0,%1,%2;" : "=l"(d) : "l"(a), "l"(b)); return d;
}
__device__ __forceinline__ u64 pk2(float lo, float hi) {
    u64 r; asm("mov.b64 %0,{%1,%2};" : "=l"(r) : "f"(lo), "f"(hi)); return r;
}
__device__ __forceinline__ void lds2(u64& a, u64& b, u32 addr) {
    asm volatile("ld.shared.v2.u64 {%0,%1},[%2];" : "=l"(a), "=l"(b) : "r"(addr));
}
__device__ __forceinline__ float4 lds4f(u32 addr) {
    float4 v;
    asm volatile("ld.shared.v4.f32 {%0,%1,%2,%3},[%4];"
                 : "=f"(v.x), "=f"(v.y), "=f"(v.z), "=f"(v.w) : "r"(addr));
    return v;
}
__device__ __forceinline__ void sts4(u32 addr, float a, float b, float c, float d) {
    asm volatile("st.shared.v4.f32 [%0],{%1,%2,%3,%4};" :: "r"(addr), "f"(a), "f"(b), "f"(c), "f"(d));
}
__device__ __forceinline__ void sts2(u32 addr, float a, float b) {
    asm volatile("st.shared.v2.f32 [%0],{%1,%2};" :: "r"(addr), "f"(a), "f"(b));
}
__device__ __forceinline__ void sts1(u32 addr, float a) {
    asm volatile("st.shared.f32 [%0],%1;" :: "r"(addr), "f"(a));
}
__device__ __forceinline__ void sts2u64(u32 addr, u64 a, u64 b) {
    asm volatile("st.shared.v2.u64 [%0],{%1,%2};" :: "r"(addr), "l"(a), "l"(b));
}
__device__ __forceinline__ u32 s2u(const void* p) {
    u32 a; asm("{.reg .u64 t; cvta.to.shared.u64 t,%1; cvt.u32.u64 %0,t;}" : "=r"(a) : "l"(p)); return a;
}

// ---------------------------------------------------------------------------
// Stage A: folded per-ring DFT.
//   re[m,bc] = sum_{q=0..nlon/2} c[q,m] * xplus[bc,q]
//   im[m,bc] = sum_{q=0..nlon/2} s[q,m] * xminus[bc,q]
// grid = (8 bc-tiles of 128, 192 rings (largest-first), 3 m-tiles of 64).
// thread tile: 4 m-pairs x 8 bc (bc in adjacent pairs -> LDS.128 loads).
// ---------------------------------------------------------------------------
extern "C" __global__ void __launch_bounds__(256, 2)
sht_stageA(const float* __restrict__ x,
           const float* __restrict__ cosb,
           const float* __restrict__ sinb)
{
    __shared__ __align__(16) unsigned char sm[2 * 16 * 512 + 2 * 16 * 1024]; // 49152
    const int t   = threadIdx.x;
    const int bc0 = blockIdx.x * 128;
    const int y   = blockIdx.y;
    const int k   = (y & 1) ? (96 + (y >> 1)) : (95 - (y >> 1));  // big rings first
    const int m0  = blockIdx.z * 64;

    int nlon, slon, mmax;
    if (k < 96) { nlon = 24 + 4 * k; slon = 2 * k * k + 22 * k; mmax = 12 + 2 * k; }
    else { int q = 192 - k; nlon = 20 + 4 * q; slon = NGRID - (2 * q * q + 22 * q); mmax = 10 + 2 * q; }
    if (mmax > MDIM - 1) mmax = MDIM - 1;
    if (m0 > mmax) return;                  // inactive m-tile: never read downstream
    const int half   = nlon >> 1;
    const int ntiles = (half + 16) >> 4;    // ceil((half+1)/16)

    const u32 sb = s2u(sm);
    const u32 CS = sb;                      // buf stride 8192, row 512 B
    const u32 XS = sb + 16384;              // buf stride 16384, row 1024 B

    const int tm = t >> 4, tb = t & 15;          // compute: 4 m-pairs, 8 bc
    const int ppb = t >> 4, mq = (t & 15) * 4;   // basis staging: 1 q-row, 4 m
    const int bcr = t >> 1, pq = (t & 1) * 8;    // x staging: 1 bc-row, 8 q

    const float* xrow  = x + (size_t)(bc0 + bcr) * NGRID + slon;
    const float* cbase = cosb + ((size_t)k * PMAX) * MDIM + m0 + mq;
    const float* sbase = sinb + ((size_t)k * PMAX) * MDIM + m0 + mq;

    u64 acc[4][8];
#pragma unroll
    for (int j = 0; j < 4; j++)
#pragma unroll
        for (int i = 0; i < 8; i++) acc[j][i] = 0ull;

    float4 c4, s4, fw0, fw1, bw0, bw1;
    float ps0, ps1;
    int p0s;
    const float4 z4 = make_float4(0.f, 0.f, 0.f, 0.f);

    auto prefetch = [&](int p0) {
        p0s = p0;
        int p = p0 + ppb;                   // p <= 207 < PMAX: in-bounds
        c4 = *(const float4*)(cbase + (size_t)p * MDIM);
        s4 = *(const float4*)(sbase + (size_t)p * MDIM);
        int q0 = p0 + pq;
        if (q0 <= half) {
            fw0 = *(const float4*)(xrow + q0);
            bw0 = *(const float4*)(xrow + nlon - q0 - 4);
            ps0 = (q0 >= 1) ? xrow[nlon - q0] : 0.f;
        } else { fw0 = z4; bw0 = z4; ps0 = 0.f; }
        int q1 = q0 + 4;
        if (q1 <= half) {
            fw1 = *(const float4*)(xrow + q1);
            bw1 = *(const float4*)(xrow + nlon - q1 - 4);
            ps1 = xrow[nlon - q1];
        } else { fw1 = z4; bw1 = z4; ps1 = 0.f; }
    };

    auto fold_emit = [&](u32 a, float4 f, float4 b, float ps, int qv) {
        float fr[4] = {f.x, f.y, f.z, f.w};
        float pr[4] = {ps, b.w, b.z, b.y};
#pragma unroll
        for (int i = 0; i < 4; i++) {
            int q = qv + i;
            bool valid = q <= half;
            bool spec  = (q == 0) || (q == half);
            float pl = valid ? (spec ? fr[i] : fr[i] + pr[i]) : 0.f;
            float mi = (valid && !spec) ? fr[i] - pr[i] : 0.f;
            sts2(a + i * 1024, pl, mi);
        }
    };

    auto store_tile = [&](int buf) {
        u32 cs = CS + buf * 8192 + ppb * 512 + mq * 8;
        sts4(cs,      c4.x, s4.x, c4.y, s4.y);
        sts4(cs + 16, c4.z, s4.z, c4.w, s4.w);
        u32 xa = XS + buf * 16384 + pq * 1024 + bcr * 8;
        int q0 = p0s + pq;
        fold_emit(xa,        fw0, bw0, ps0, q0);
        fold_emit(xa + 4096, fw1, bw1, ps1, q0 + 4);
    };

    auto compute = [&](int buf) {
        u32 cs = CS + buf * 8192 + tm * 32;
        u32 xs = XS + buf * 16384 + tb * 16;
#pragma unroll
        for (int pp = 0; pp < 16; ++pp) {
            u64 b0, b1, b2, b3;
            lds2(b0, b1, cs + pp * 512);
            lds2(b2, b3, cs + pp * 512 + 16);
            u64 v[8];
            lds2(v[0], v[1], xs + pp * 1024);
            lds2(v[2], v[3], xs + pp * 1024 + 256);
            lds2(v[4], v[5], xs + pp * 1024 + 512);
            lds2(v[6], v[7], xs + pp * 1024 + 768);
#pragma unroll
            for (int i = 0; i < 8; i++) {
                acc[0][i] = ffma2(b0, v[i], acc[0][i]);
                acc[1][i] = ffma2(b1, v[i], acc[1][i]);
                acc[2][i] = ffma2(b2, v[i], acc[2][i]);
                acc[3][i] = ffma2(b3, v[i], acc[3][i]);
            }
        }
    };

    prefetch(0);
    store_tile(0);
    __syncthreads();
    for (int ti = 0; ti < ntiles; ++ti) {
        bool nx = (ti + 1) < ntiles;
        if (nx) prefetch((ti + 1) << 4);
        compute(ti & 1);
        if (nx) store_tile((ti + 1) & 1);
        __syncthreads();
    }

    const u64 tp2 = pk2(TWO_PI_F, TWO_PI_F);
#pragma unroll
    for (int j = 0; j < 4; j++) {
        u64* o = g_ri + (((size_t)(m0 + tm * 4 + j)) * KR + k) * BCN + bc0 + tb * 2;
#pragma unroll
        for (int i = 0; i < 4; i++) {
            ulonglong2 w;
            w.x = fmul2(acc[j][2 * i], tp2);
            w.y = fmul2(acc[j][2 * i + 1], tp2);
            *(ulonglong2*)(o + i * 32) = w;
        }
    }
}

// ---------------------------------------------------------------------------
// Stage B: per-m GEMM with hemisphere parity fold.
//   weight[m,l,k] = (-1)^(l+m) weight[m,l,191-k]
//   A+/-[k] = A[k] +/- A[191-k],  k in [klo, 95]
//   st[m,l,bc] = sum_k W[m,l,k] * ( (l+m) even ? A+[k] : A-[k] )
// grid = (16 bc-tiles of 64, 3 l-tiles of 64, 192 m), block = 128.
// thread tile: 8 l x 4 bc (bc pairs {2tb,2tb+1} and {2tb+32,2tb+33}).
// ---------------------------------------------------------------------------
extern "C" __global__ void __launch_bounds__(128, 4)
sht_stageB(const float* __restrict__ weight)
{
    __shared__ __align__(16) unsigned char sm[4 * 16 * 512 + 2 * 16 * 272];  // 41472
    const int t   = threadIdx.x;
    const int bc0 = blockIdx.x * 64;
    const int l0  = blockIdx.y * 64;
    const int m   = blockIdx.z;
    if (l0 + 63 < m) return;                // zero triangle: handled by transpose

    const int tb = t & 15, tl = t >> 4;     // 4 bc, 8 l per thread

    const int klo = (m <= 12) ? 0 : ((m - 11) >> 1);   // klo <= 90 < 96
    const int kb0 = klo & ~15;
    const int nkt = ((95 - kb0) >> 4) + 1;  // folded range [kb0, 95], exact tiles

    const u32 sb  = s2u(sm);
    const u32 APS = sb;                     // A+ : buf stride 8192, row 512 B
    const u32 AMS = sb + 16384;             // A- : buf stride 8192, row 512 B
    const u32 WS  = sb + 32768;             // W  : buf stride 4352, row 272 B

    // staging roles
    const int ska = t >> 3, sc8 = (t & 7) * 8;     // A: 1 k-row, 8 bc (u64)
    const int lr = t >> 1, kq = (t & 1) * 8;       // W: 1 l-row, 8 k

    const float* wrow  = weight + ((size_t)m * MDIM + l0 + lr) * KR;
    const u64*   abase = g_ri + ((size_t)m * KR) * BCN + bc0 + sc8;

    u64 acc[8][4];
#pragma unroll
    for (int j = 0; j < 8; j++)
#pragma unroll
        for (int i = 0; i < 4; i++) acc[j][i] = 0ull;

    const u64 NEG1 = pk2(-1.f, -1.f);

    ulonglong2 ra[4], rb[4];
    float4 w40, w41;
    int kvalid;

    auto ldA = [&](int kb) {
        int kg = kb + ska;                  // kg <= 95 always
        kvalid = (kg >= klo);
        int kgc = kvalid ? kg : klo;
        const u64* s0 = abase + (size_t)kgc * BCN;
        const u64* s1 = abase + (size_t)(191 - kgc) * BCN;
#pragma unroll
        for (int i = 0; i < 4; i++) {
            ra[i] = *(const ulonglong2*)(s0 + 2 * i);
            rb[i] = *(const ulonglong2*)(s1 + 2 * i);
        }
    };
    auto ldW = [&](int kb) {
        w40 = *(const float4*)(wrow + kb + kq);
        w41 = *(const float4*)(wrow + kb + kq + 4);
    };
    auto stA = [&](int buf) {
        u32 ap = APS + buf * 8192 + ska * 512 + sc8 * 8;
        u32 am = AMS + buf * 8192 + ska * 512 + sc8 * 8;
#pragma unroll
        for (int i = 0; i < 4; i++) {
            u64 px, py, mx, my;
            if (kvalid) {
                px = fadd2(ra[i].x, rb[i].x);  py = fadd2(ra[i].y, rb[i].y);
                mx = ffma2(rb[i].x, NEG1, ra[i].x);
                my = ffma2(rb[i].y, NEG1, ra[i].y);
            } else { px = py = mx = my = 0ull; }
            sts2u64(ap + i * 16, px, py);
            sts2u64(am + i * 16, mx, my);
        }
    };
    auto stW = [&](int buf) {
        u32 ws = WS + buf * 4352 + kq * 272 + lr * 4;
        sts1(ws,           w40.x); sts1(ws + 272,     w40.y);
        sts1(ws + 2 * 272, w40.z); sts1(ws + 3 * 272, w40.w);
        sts1(ws + 4 * 272, w41.x); sts1(ws + 5 * 272, w41.y);
        sts1(ws + 6 * 272, w41.z); sts1(ws + 7 * 272, w41.w);
    };

    // even-j rows (l = l0+tl*8+j) have parity (j+m)&1 -> base pointer select once
    const u32 PE = (m & 1) ? AMS : APS;     // j even
    const u32 PO = (m & 1) ? APS : AMS;     // j odd

    auto compute = [&](int buf) {
        u32 pe = PE + buf * 8192 + tb * 16;
        u32 po = PO + buf * 8192 + tb * 16;
        u32 ws = WS + buf * 4352 + tl * 32;
#pragma unroll
        for (int kk = 0; kk < 16; ++kk) {
            u64 e[4], o4[4];
            lds2(e[0],  e[1],  pe + kk * 512);
            lds2(e[2],  e[3],  pe + kk * 512 + 256);
            lds2(o4[0], o4[1], po + kk * 512);
            lds2(o4[2], o4[3], po + kk * 512 + 256);
            float4 f0 = lds4f(ws + kk * 272);
            float4 f1 = lds4f(ws + kk * 272 + 16);
            const float fw[8] = {f0.x, f0.y, f0.z, f0.w, f1.x, f1.y, f1.z, f1.w};
#pragma unroll
            for (int j = 0; j < 8; j++) {
                u64 ww = pk2(fw[j], fw[j]);
                const u64* src = (j & 1) ? o4 : e;
#pragma unroll
                for (int i = 0; i < 4; i++)
                    acc[j][i] = ffma2(src[i], ww, acc[j][i]);
            }
        }
    };

    ldA(kb0);
    ldW(kb0);
    stA(0);
    stW(0);
    __syncthreads();
    for (int ti = 0; ti < nkt; ++ti) {
        int kb = kb0 + ((ti + 1) << 4);
        bool nx = (ti + 1) < nkt;
        if (nx) { ldA(kb); ldW(kb); }
        compute(ti & 1);
        if (nx) { stA((ti + 1) & 1); stW((ti + 1) & 1); }
        __syncthreads();
    }

    // coalesced staging writes: [m][l][bc]; thread bc = 2tb,2tb+1, +32
#pragma unroll
    for (int j = 0; j < 8; j++) {
        u64* o = g_st + (((size_t)m * MDIM) + l0 + tl * 8 + j) * BCN + bc0 + tb * 2;
        ulonglong2 w0, w1;
        w0.x = acc[j][0]; w0.y = acc[j][1];
        w1.x = acc[j][2]; w1.y = acc[j][3];
        *(ulonglong2*)o        = w0;
        *(ulonglong2*)(o + 32) = w1;
    }
}

// ---------------------------------------------------------------------------
// Transpose: out[bc][l][m] <- g_st[m][l][bc]; zero for l < m.
// grid = (16 bc-tiles of 64, 6 m-tiles of 32, 192 l), block = 256.
// ---------------------------------------------------------------------------
extern "C" __global__ void __launch_bounds__(256)
sht_transpose(u64* __restrict__ out)
{
    __shared__ u64 smt[32][65];
    const int t   = threadIdx.x;
    const int bc0 = blockIdx.x * 64;
    const int m0  = blockIdx.y * 32;
    const int l   = blockIdx.z;

    // load: rows = m (contig bc), with zero for l < m
    const int mr  = t >> 5;            // 0..7
    const int bcc = (t & 31) * 2;      // 0..62
#pragma unroll
    for (int r = 0; r < 4; ++r) {
        int ml = mr + r * 8;
        ulonglong2 v;
        if (l >= m0 + ml)
            v = *(const ulonglong2*)(g_st + (((size_t)(m0 + ml)) * MDIM + l) * BCN + bc0 + bcc);
        else
            v = make_ulonglong2(0ull, 0ull);
        smt[ml][bcc]     = v.x;
        smt[ml][bcc + 1] = v.y;
    }
    __syncthreads();

    // store: rows = bc (contig m)
    const int bcr = t >> 4;            // 0..15
    const int mc  = (t & 15) * 2;      // 0..30
#pragma unroll
    for (int r = 0; r < 4; ++r) {
        int bcl = bcr + r * 16;
        ulonglong2 v;
        v.x = smt[mc][bcl];
        v.y = smt[mc + 1][bcl];
        *(ulonglong2*)(out + (((size_t)(bc0 + bcl)) * MDIM + l) * MDIM + m0 + mc) = v;
    }
}

// ---------------------------------------------------------------------------

extern "C" void kernel_launch(void* const* d_in, const int* in_sizes, int n_in,
                              void* d_out, int out_size)
{
    (void)in_sizes; (void)n_in; (void)out_size;
    const float* x      = (const float*)d_in[0];
    const float* weight = (const float*)d_in[1];
    const float* cosb   = (const float*)d_in[2];
    const float* sinb   = (const float*)d_in[3];

    dim3 gA(8, 192, 3);
    sht_stageA<<<gA, 256>>>(x, cosb, sinb);

    dim3 gB(16, 3, 192);
    sht_stageB<<<gB, 128>>>(weight);

    dim3 gT(16, 6, 192);
    sht_transpose<<<gT, 256>>>((u64*)d_out);
}